// round 9
// baseline (speedup 1.0000x reference)
#include <cuda_runtime.h>
#include <cuda_fp16.h>
#include <cstdint>
#include <cstddef>

#define D 128
#define MAXN 50000
#define MAXE 800000
#define BN_EPS 1e-5f
#define SCAN_B 1024
#define NBLK ((MAXN + SCAN_B - 1) / SCAN_B)   // 49
#define TGRID 296                              // 2 persistent CTAs per SM

// ---------------- device scratch ----------------
__device__ __half2 g_x16[(size_t)MAXN * 64];    // fp16 x
__device__ __half2 g_h16[(size_t)MAXN * 64];    // fp16 h (relu(bn(h)) in place later)
__device__ __half2 g_agg16[(size_t)MAXN * 64];  // fp16 neighbor mean
__device__ __half2 g_bf1[16 * 16 * 32 * 2];     // layer-1 B fragments
__device__ __half2 g_bf2[16 * 16 * 32 * 2];     // layer-2 B fragments
__device__ int    g_cnt[MAXN];
__device__ int    g_offs[MAXN + 1];
__device__ int    g_cur[MAXN];
__device__ int    g_esrc[MAXE];
__device__ int    g_ipfx[NBLK];
__device__ volatile int g_sflag[NBLK];
__device__ int    g_done;
__device__ volatile int g_ready;
__device__ float  g_colsum[D], g_colsumsq[D], g_scale[D], g_shift[D];

// ---------------- helpers ----------------
__device__ __forceinline__ void red_add1(float* p, float v) {
    asm volatile("red.global.add.f32 [%0], %1;" :: "l"(p), "f"(v) : "memory");
}
__device__ __forceinline__ void mma16816(float* c, uint32_t a0, uint32_t a1,
                                         uint32_t a2, uint32_t a3,
                                         uint32_t b0, uint32_t b1) {
    asm volatile("mma.sync.aligned.m16n8k16.row.col.f32.f16.f16.f32 "
                 "{%0,%1,%2,%3}, {%4,%5,%6,%7}, {%8,%9}, {%0,%1,%2,%3};"
                 : "+f"(c[0]), "+f"(c[1]), "+f"(c[2]), "+f"(c[3])
                 : "r"(a0), "r"(a1), "r"(a2), "r"(a3), "r"(b0), "r"(b1));
}

// ---------------- fused setup: zero scratch + conv x->fp16 + B fragments ---------
// block partition: [0, zb) zero | [zb, zb+64) bfrag | [zb+64, ...) conv
__global__ void setup_k(const float* __restrict__ x,
                        const float* __restrict__ w1l, const float* __restrict__ w1r,
                        const float* __restrict__ w2l, const float* __restrict__ w2r,
                        int N, int zb) {
    int b = blockIdx.x, t = threadIdx.x;
    if (b < zb) {
        int i = b * 256 + t;
        if (i < N) g_cnt[i] = 0;
        else if (i < N + 128) g_colsum[i - N] = 0.f;
        else if (i < N + 256) g_colsumsq[i - N - 128] = 0.f;
        else if (i < N + 256 + NBLK) g_sflag[i - N - 256] = 0;
        else if (i == N + 256 + NBLK)     g_done = 0;
        else if (i == N + 256 + NBLK + 1) g_ready = 0;
        return;
    }
    if (b < zb + 64) {
        // B fragment precompute: m16n8k16 B frag, lane t%32 holds
        // {B[k0+2(t%4)][n], B[k0+2(t%4)+1][n]} and same at k+8; n = nt*8 + t/4
        int idx = (b - zb) * 256 + t;        // 0..16383
        int layer = idx >> 13;
        int slot  = idx & 8191;              // (ks*16+nt)*32 + lane
        int lane  = slot & 31;
        int fk    = slot >> 5;
        int ks = fk >> 4, nt = fk & 15;
        int n  = nt * 8 + (lane >> 2);
        int k0 = ks * 16 + 2 * (lane & 3);
        const float* wl = layer ? w2l : w1l;
        const float* wr = layer ? w2r : w1r;
        auto W = [&](int k) { return (k < 128) ? wl[n * 128 + k] : wr[n * 128 + k - 128]; };
        __half2* dst = (layer ? g_bf2 : g_bf1) + (size_t)slot * 2;
        dst[0] = __floats2half2_rn(W(k0),     W(k0 + 1));
        dst[1] = __floats2half2_rn(W(k0 + 8), W(k0 + 9));
        return;
    }
    int i = (b - zb - 64) * 256 + t;         // float4 index over x
    if (i >= N * 32) return;
    float4 v = __ldg((const float4*)x + i);
    g_x16[(size_t)i * 2]     = __floats2half2_rn(v.x, v.y);
    g_x16[(size_t)i * 2 + 1] = __floats2half2_rn(v.z, v.w);
}

// ---------------- CSR build ----------------
__global__ void hist_k(const int* __restrict__ ei, int E) {
    int e = blockIdx.x * blockDim.x + threadIdx.x;
    if (e < E) atomicAdd(&g_cnt[ei[E + e]], 1);
}

// domino scan: local 1024-scan + chained cross-block prefix (49 blocks, all resident)
__global__ void scan_k(int n, int E) {
    __shared__ int sm[SCAN_B];
    __shared__ int sPrev;
    int b = blockIdx.x, t = threadIdx.x, i = b * SCAN_B + t;
    int v = (i < n) ? g_cnt[i] : 0;
    sm[t] = v; __syncthreads();
    int acc = v;
    #pragma unroll
    for (int off = 1; off < SCAN_B; off <<= 1) {
        int add = (t >= off) ? sm[t - off] : 0;
        __syncthreads();
        acc += add; sm[t] = acc;
        __syncthreads();
    }
    // sm[SCAN_B-1] = block total; chain the prefix through previous block
    if (t == 0) {
        int prev = 0;
        if (b > 0) {
            while (g_sflag[b - 1] == 0) __nanosleep(100);
            __threadfence();
            prev = g_ipfx[b - 1];
        }
        g_ipfx[b] = prev + sm[SCAN_B - 1];
        __threadfence();
        g_sflag[b] = 1;
        sPrev = prev;
    }
    __syncthreads();
    if (i < n) {
        int o = acc - v + sPrev;       // exclusive + cross-block prefix
        g_offs[i] = o;
        g_cur[i] = o;
    }
    if (i == n) g_offs[n] = E;
}

__global__ void fill_k(const int* __restrict__ ei, int E) {
    int e = blockIdx.x * blockDim.x + threadIdx.x;
    if (e < E) {
        int d = ei[E + e];
        int pos = atomicAdd(&g_cur[d], 1);
        g_esrc[pos] = ei[e];
    }
}

// ---------------- gather v2: one warp per node, LDG.64 per edge per lane ---------
__global__ void gather_k(const __half2* __restrict__ feat, int N) {
    int gw = (blockIdx.x * blockDim.x + threadIdx.x) >> 5;
    int lane = threadIdx.x & 31;
    if (gw >= N) return;
    int s0 = g_offs[gw], s1 = g_offs[gw + 1];
    const uint2* f = (const uint2*)feat;            // row = 32 uint2 (256B)
    float4 acc = make_float4(0.f, 0.f, 0.f, 0.f);
    int e = s0;
    for (; e + 2 <= s1; e += 2) {
        int a = g_esrc[e], b = g_esrc[e + 1];
        uint2 va = __ldg(f + (size_t)a * 32 + lane);
        uint2 vb = __ldg(f + (size_t)b * 32 + lane);
        float2 fa0 = __half22float2(*(__half2*)&va.x);
        float2 fa1 = __half22float2(*(__half2*)&va.y);
        float2 fb0 = __half22float2(*(__half2*)&vb.x);
        float2 fb1 = __half22float2(*(__half2*)&vb.y);
        acc.x += fa0.x + fb0.x; acc.y += fa0.y + fb0.y;
        acc.z += fa1.x + fb1.x; acc.w += fa1.y + fb1.y;
    }
    if (e < s1) {
        int a = g_esrc[e];
        uint2 va = __ldg(f + (size_t)a * 32 + lane);
        float2 fa0 = __half22float2(*(__half2*)&va.x);
        float2 fa1 = __half22float2(*(__half2*)&va.y);
        acc.x += fa0.x; acc.y += fa0.y; acc.z += fa1.x; acc.w += fa1.y;
    }
    float inv = 1.0f / fmaxf((float)(s1 - s0), 1.0f);
    uint2 o;
    *(__half2*)&o.x = __floats2half2_rn(acc.x * inv, acc.y * inv);
    *(__half2*)&o.y = __floats2half2_rn(acc.z * inv, acc.w * inv);
    ((uint2*)g_agg16)[(size_t)gw * 32 + lane] = o;
}

// ---------------- HMMA node transform ----------------
template<bool OUT_HALF>
__global__ void __launch_bounds__(256, 2)
mma_transform_k(const uint32_t* __restrict__ aggH,   // [m][64] half2-as-u32
                const uint32_t* __restrict__ selfH,
                const uint2* __restrict__ bfrag,     // 8192 x 8B fragments
                const float* __restrict__ bias,
                float* __restrict__ outF, __half2* __restrict__ outH,
                int nNodes, int ntiles) {
    extern __shared__ char smraw[];
    uint2* sB = (uint2*)smraw;                        // 64KB
    float* sBias = (float*)(smraw + 65536);
    int tid = threadIdx.x;
    for (int i = tid; i < 8192; i += 256) sB[i] = __ldg(bfrag + i);
    if (tid < 128) sBias[tid] = __ldg(bias + tid);
    __syncthreads();

    int warp = tid >> 5, lane = tid & 31;
    int r = lane >> 2, c = lane & 3;

    for (int tile = blockIdx.x; tile < ntiles; tile += gridDim.x) {
        int m0 = tile * 128 + warp * 16;
        size_t row0 = (size_t)min(m0 + r,     nNodes - 1);
        size_t row1 = (size_t)min(m0 + r + 8, nNodes - 1);
        const uint32_t* p0a = aggH  + row0 * 64 + c;
        const uint32_t* p1a = aggH  + row1 * 64 + c;
        const uint32_t* p0s = selfH + row0 * 64 + c;
        const uint32_t* p1s = selfH + row1 * 64 + c;

        float acc[16][4];
        #pragma unroll
        for (int nt = 0; nt < 16; nt++)
            #pragma unroll
            for (int q = 0; q < 4; q++) acc[nt][q] = 0.f;

        #pragma unroll
        for (int ks = 0; ks < 16; ks++) {
            const uint32_t* p0 = (ks < 8) ? p0a + ks * 8 : p0s + (ks - 8) * 8;
            const uint32_t* p1 = (ks < 8) ? p1a + ks * 8 : p1s + (ks - 8) * 8;
            uint32_t a0 = __ldg(p0), a2 = __ldg(p0 + 4);
            uint32_t a1 = __ldg(p1), a3 = __ldg(p1 + 4);
            const uint2* bp = sB + ks * 512 + lane;
            #pragma unroll
            for (int nt = 0; nt < 16; nt++) {
                uint2 b = bp[nt * 32];
                mma16816(acc[nt], a0, a1, a2, a3, b.x, b.y);
            }
        }

        bool ok0 = (m0 + r)     < nNodes;
        bool ok1 = (m0 + r + 8) < nNodes;
        #pragma unroll
        for (int nt = 0; nt < 16; nt++) {
            int j = nt * 8 + 2 * c;
            float b0 = sBias[j], b1 = sBias[j + 1];
            float v0 = acc[nt][0] + b0, v1 = acc[nt][1] + b1;
            float v2 = acc[nt][2] + b0, v3 = acc[nt][3] + b1;
            if (OUT_HALF) {
                if (ok0) outH[(size_t)(m0 + r)     * 64 + (j >> 1)] = __floats2half2_rn(v0, v1);
                if (ok1) outH[(size_t)(m0 + r + 8) * 64 + (j >> 1)] = __floats2half2_rn(v2, v3);
            } else {
                if (ok0) *(float2*)(outF + (size_t)(m0 + r)     * 128 + j) = make_float2(v0, v1);
                if (ok1) *(float2*)(outF + (size_t)(m0 + r + 8) * 128 + j) = make_float2(v2, v3);
            }
        }
    }
}

// ---------------- fused BN: stats -> finalize -> relu(bn(h)) in one kernel -------
// persistent 296 blocks (all resident); last-block finalize + ready-flag barrier
__global__ void __launch_bounds__(256, 2)
bnfuse_k(const float* __restrict__ gamma, const float* __restrict__ beta,
         float invN, int N) {
    int t = threadIdx.x;
    int c2  = t & 63;
    int sub = t >> 6;      // 0..3
    float sx = 0.f, sy = 0.f, qx = 0.f, qy = 0.f;
    for (int row = blockIdx.x * 4 + sub; row < N; row += gridDim.x * 4) {
        float2 f = __half22float2(g_h16[(size_t)row * 64 + c2]);
        sx += f.x; sy += f.y; qx += f.x * f.x; qy += f.y * f.y;
    }
    red_add1(g_colsum   + 2 * c2,     sx);
    red_add1(g_colsum   + 2 * c2 + 1, sy);
    red_add1(g_colsumsq + 2 * c2,     qx);
    red_add1(g_colsumsq + 2 * c2 + 1, qy);
    __threadfence();
    __shared__ int isLast;
    __syncthreads();
    if (t == 0) isLast = (atomicAdd(&g_done, 1) == gridDim.x - 1);
    __syncthreads();
    if (isLast) {
        if (t < 128) {
            int j = t;
            float mu  = __ldcg(g_colsum + j) * invN;
            float var = __ldcg(g_colsumsq + j) * invN - mu * mu;
            float sc  = __ldg(gamma + j) * rsqrtf(var + BN_EPS);
            g_scale[j] = sc;
            g_shift[j] = fmaf(-mu, sc, __ldg(beta + j));
        }
        __threadfence();
        __syncthreads();
        if (t == 0) g_ready = 1;
    }
    if (t == 0) {
        while (g_ready == 0) __nanosleep(100);
    }
    __syncthreads();
    __threadfence();
    // apply relu(bn(.)) in place on h16
    float sc0 = __ldcg(g_scale + 2 * c2),     sc1 = __ldcg(g_scale + 2 * c2 + 1);
    float sh0 = __ldcg(g_shift + 2 * c2),     sh1 = __ldcg(g_shift + 2 * c2 + 1);
    for (int row = blockIdx.x * 4 + sub; row < N; row += gridDim.x * 4) {
        size_t idx = (size_t)row * 64 + c2;
        float2 f = __half22float2(g_h16[idx]);
        f.x = fmaxf(fmaf(f.x, sc0, sh0), 0.f);
        f.y = fmaxf(fmaf(f.y, sc1, sh1), 0.f);
        g_h16[idx] = __floats2half2_rn(f.x, f.y);
    }
}

// ---------------- launch ----------------
extern "C" void kernel_launch(void* const* d_in, const int* in_sizes, int n_in,
                              void* d_out, int out_size) {
    const float* x     = (const float*)d_in[0];
    const int*   ei    = (const int*)d_in[1];     // int32
    const float* w1l   = (const float*)d_in[2];
    const float* b1l   = (const float*)d_in[3];
    const float* w1r   = (const float*)d_in[4];
    const float* w2l   = (const float*)d_in[5];
    const float* b2l   = (const float*)d_in[6];
    const float* w2r   = (const float*)d_in[7];
    const float* gamma = (const float*)d_in[8];
    const float* beta  = (const float*)d_in[9];
    float*       out   = (float*)d_out;

    int N = in_sizes[0] / D;
    int E = in_sizes[1] / 2;
    int ntiles = (N + 127) / 128;

    void *p_x16, *p_h16, *p_agg16, *p_bf1, *p_bf2;
    cudaGetSymbolAddress(&p_x16,   g_x16);
    cudaGetSymbolAddress(&p_h16,   g_h16);
    cudaGetSymbolAddress(&p_agg16, g_agg16);
    cudaGetSymbolAddress(&p_bf1,   g_bf1);
    cudaGetSymbolAddress(&p_bf2,   g_bf2);

    int smem = 65536 + 512;
    cudaFuncSetAttribute(mma_transform_k<true>,
                         cudaFuncAttributeMaxDynamicSharedMemorySize, smem);
    cudaFuncSetAttribute(mma_transform_k<false>,
                         cudaFuncAttributeMaxDynamicSharedMemorySize, smem);

    // fused setup: zeros (N + 256 + NBLK + 2 words) + 64 bfrag blocks + conv blocks
    int zb = (N + 256 + NBLK + 2 + 255) / 256;
    int cb = (N * 32 + 255) / 256;
    setup_k<<<zb + 64 + cb, 256>>>(x, w1l, w1r, w2l, w2r, N, zb);

    // CSR build (reused by both layers)
    int egrid = (E + 255) / 256;
    hist_k<<<egrid, 256>>>(ei, E);
    scan_k<<<NBLK, SCAN_B>>>(N, E);
    fill_k<<<egrid, 256>>>(ei, E);

    int ggrid = (N * 32 + 255) / 256;

    // layer 1: h = mean(x_nbr)@W1l + b1 + x@W1r   (fp16 inputs, fp32 acc)
    gather_k<<<ggrid, 256>>>((const __half2*)p_x16, N);
    mma_transform_k<true><<<TGRID, 256, smem>>>(
        (const uint32_t*)p_agg16, (const uint32_t*)p_x16,
        (const uint2*)p_bf1, b1l, nullptr, (__half2*)p_h16, N, ntiles);

    // fused BN: stats + finalize + relu(bn(h)) in place
    bnfuse_k<<<TGRID, 256>>>(gamma, beta, 1.0f / (float)N, N);

    // layer 2: out = mean(rbh_nbr)@W2l + b2 + rbh@W2r
    gather_k<<<ggrid, 256>>>((const __half2*)p_h16, N);
    mma_transform_k<false><<<TGRID, 256, smem>>>(
        (const uint32_t*)p_agg16, (const uint32_t*)p_h16,
        (const uint2*)p_bf2, b2l, out, nullptr, N, ntiles);
}

// round 10
// speedup vs baseline: 1.3206x; 1.3206x over previous
#include <cuda_runtime.h>
#include <cuda_fp16.h>
#include <cstdint>
#include <cstddef>

#define D 128
#define MAXN 50000
#define MAXE 800000
#define BN_EPS 1e-5f
#define SCAN_B 1024
#define NBLK ((MAXN + SCAN_B - 1) / SCAN_B)   // 49
#define TGRID 296                              // 2 persistent CTAs per SM

// ---------------- device scratch (zero-initialized at module load; every kernel
// that consumes a counter restores it to zero for the next replay) ----------------
__device__ __half2 g_x16[(size_t)MAXN * 64];    // fp16 x; reused as rbh after layer 1
__device__ __half2 g_h16[(size_t)MAXN * 64];    // fp16 h
__device__ __half2 g_agg16[(size_t)MAXN * 64];  // fp16 neighbor mean
__device__ __half2 g_bf1[16 * 16 * 32 * 2];     // layer-1 B fragments
__device__ __half2 g_bf2[16 * 16 * 32 * 2];     // layer-2 B fragments
__device__ int    g_cnt[MAXN];                  // zeroed by scan_local after use
__device__ int    g_offs[MAXN + 1];
__device__ int    g_cur[MAXN];
__device__ int    g_bsum[NBLK];
__device__ int    g_esrc[MAXE];
__device__ int    g_done;                       // zeroed by stats_k last block
__device__ float  g_colsum[D], g_colsumsq[D];   // zeroed by stats_k last block
__device__ float  g_scale[D], g_shift[D];

// ---------------- helpers ----------------
__device__ __forceinline__ void red_add1(float* p, float v) {
    asm volatile("red.global.add.f32 [%0], %1;" :: "l"(p), "f"(v) : "memory");
}
__device__ __forceinline__ void mma16816(float* c, uint32_t a0, uint32_t a1,
                                         uint32_t a2, uint32_t a3,
                                         uint32_t b0, uint32_t b1) {
    asm volatile("mma.sync.aligned.m16n8k16.row.col.f32.f16.f16.f32 "
                 "{%0,%1,%2,%3}, {%4,%5,%6,%7}, {%8,%9}, {%0,%1,%2,%3};"
                 : "+f"(c[0]), "+f"(c[1]), "+f"(c[2]), "+f"(c[3])
                 : "r"(a0), "r"(a1), "r"(a2), "r"(a3), "r"(b0), "r"(b1));
}

// ---------------- fused setup: conv x->fp16 + B fragments ----------------
// block partition: [0, 64) bfrag | [64, ...) conv
__global__ void setup_k(const float* __restrict__ x,
                        const float* __restrict__ w1l, const float* __restrict__ w1r,
                        const float* __restrict__ w2l, const float* __restrict__ w2r,
                        int N) {
    int b = blockIdx.x, t = threadIdx.x;
    if (b < 64) {
        // B fragment precompute: m16n8k16 B frag, lane t%32 holds
        // {B[k0+2(t%4)][n], B[k0+2(t%4)+1][n]} and same at k+8; n = nt*8 + t/4
        int idx = b * 256 + t;               // 0..16383
        int layer = idx >> 13;
        int slot  = idx & 8191;              // (ks*16+nt)*32 + lane
        int lane  = slot & 31;
        int fk    = slot >> 5;
        int ks = fk >> 4, nt = fk & 15;
        int n  = nt * 8 + (lane >> 2);
        int k0 = ks * 16 + 2 * (lane & 3);
        const float* wl = layer ? w2l : w1l;
        const float* wr = layer ? w2r : w1r;
        auto W = [&](int k) { return (k < 128) ? wl[n * 128 + k] : wr[n * 128 + k - 128]; };
        __half2* dst = (layer ? g_bf2 : g_bf1) + (size_t)slot * 2;
        dst[0] = __floats2half2_rn(W(k0),     W(k0 + 1));
        dst[1] = __floats2half2_rn(W(k0 + 8), W(k0 + 9));
        return;
    }
    int i = (b - 64) * 256 + t;              // float4 index over x
    if (i >= N * 32) return;
    float4 v = __ldg((const float4*)x + i);
    g_x16[(size_t)i * 2]     = __floats2half2_rn(v.x, v.y);
    g_x16[(size_t)i * 2 + 1] = __floats2half2_rn(v.z, v.w);
}

// ---------------- CSR build ----------------
__global__ void hist_k(const int* __restrict__ ei, int E) {
    int e = blockIdx.x * blockDim.x + threadIdx.x;
    if (e < E) atomicAdd(&g_cnt[ei[E + e]], 1);
}

__global__ void scan_local_k(int n) {
    __shared__ int sm[SCAN_B];
    int t = threadIdx.x, i = blockIdx.x * SCAN_B + t;
    int v = (i < n) ? g_cnt[i] : 0;
    if (i < n) g_cnt[i] = 0;                 // reset for next replay
    sm[t] = v; __syncthreads();
    int acc = v;
    #pragma unroll
    for (int off = 1; off < SCAN_B; off <<= 1) {
        int add = (t >= off) ? sm[t - off] : 0;
        __syncthreads();
        acc += add; sm[t] = acc;
        __syncthreads();
    }
    if (i < n) g_offs[i] = acc - v;
    if (t == SCAN_B - 1) g_bsum[blockIdx.x] = acc;
}

// scan_add with the 49-entry block-sum scan done redundantly per block
__global__ void scan_add_k(int n, int E) {
    __shared__ int sb[64];
    int t = threadIdx.x;
    int orig = 0;
    if (t < 64) { orig = (t < NBLK) ? g_bsum[t] : 0; sb[t] = orig; }
    __syncthreads();
    #pragma unroll
    for (int off = 1; off < 64; off <<= 1) {
        int add = 0;
        if (t < 64 && t >= off) add = sb[t - off];
        __syncthreads();
        if (t < 64) sb[t] += add;
        __syncthreads();
    }
    if (t < 64) sb[t] -= orig;        // inclusive -> exclusive
    __syncthreads();
    int i = blockIdx.x * blockDim.x + t;
    if (i < n) {
        int o = g_offs[i] + sb[i >> 10];    // SCAN_B = 1024
        g_offs[i] = o;
        g_cur[i] = o;
    }
    if (i == n) g_offs[n] = E;
}

__global__ void fill_k(const int* __restrict__ ei, int E) {
    int e = blockIdx.x * blockDim.x + threadIdx.x;
    if (e < E) {
        int d = ei[E + e];
        int pos = atomicAdd(&g_cur[d], 1);
        g_esrc[pos] = ei[e];
    }
}

// ---------------- gather: one warp per node, LDG.64 per edge per lane -----------
// BN variant applies relu(bn(.)) per neighbor (pre-mean, fp32) and also writes
// this node's relu(bn(h)) row to rbh for the transform's self path.
template<bool BN>
__global__ void gather_k(const __half2* __restrict__ feat, uint2* __restrict__ rbh,
                         int N) {
    int gw = (blockIdx.x * blockDim.x + threadIdx.x) >> 5;
    int lane = threadIdx.x & 31;
    if (gw >= N) return;
    int s0 = g_offs[gw], s1 = g_offs[gw + 1];
    float4 sc, sh;
    if (BN) {
        sc = ((const float4*)g_scale)[lane];
        sh = ((const float4*)g_shift)[lane];
    }
    const uint2* f = (const uint2*)feat;            // row = 32 uint2 (256B)
    float4 acc = make_float4(0.f, 0.f, 0.f, 0.f);
    int e = s0;
    for (; e + 2 <= s1; e += 2) {
        int a = g_esrc[e], b = g_esrc[e + 1];
        uint2 va = __ldg(f + (size_t)a * 32 + lane);
        uint2 vb = __ldg(f + (size_t)b * 32 + lane);
        float2 fa0 = __half22float2(*(__half2*)&va.x);
        float2 fa1 = __half22float2(*(__half2*)&va.y);
        float2 fb0 = __half22float2(*(__half2*)&vb.x);
        float2 fb1 = __half22float2(*(__half2*)&vb.y);
        if (BN) {
            fa0.x = fmaxf(fmaf(fa0.x, sc.x, sh.x), 0.f);
            fa0.y = fmaxf(fmaf(fa0.y, sc.y, sh.y), 0.f);
            fa1.x = fmaxf(fmaf(fa1.x, sc.z, sh.z), 0.f);
            fa1.y = fmaxf(fmaf(fa1.y, sc.w, sh.w), 0.f);
            fb0.x = fmaxf(fmaf(fb0.x, sc.x, sh.x), 0.f);
            fb0.y = fmaxf(fmaf(fb0.y, sc.y, sh.y), 0.f);
            fb1.x = fmaxf(fmaf(fb1.x, sc.z, sh.z), 0.f);
            fb1.y = fmaxf(fmaf(fb1.y, sc.w, sh.w), 0.f);
        }
        acc.x += fa0.x + fb0.x; acc.y += fa0.y + fb0.y;
        acc.z += fa1.x + fb1.x; acc.w += fa1.y + fb1.y;
    }
    if (e < s1) {
        int a = g_esrc[e];
        uint2 va = __ldg(f + (size_t)a * 32 + lane);
        float2 fa0 = __half22float2(*(__half2*)&va.x);
        float2 fa1 = __half22float2(*(__half2*)&va.y);
        if (BN) {
            fa0.x = fmaxf(fmaf(fa0.x, sc.x, sh.x), 0.f);
            fa0.y = fmaxf(fmaf(fa0.y, sc.y, sh.y), 0.f);
            fa1.x = fmaxf(fmaf(fa1.x, sc.z, sh.z), 0.f);
            fa1.y = fmaxf(fmaf(fa1.y, sc.w, sh.w), 0.f);
        }
        acc.x += fa0.x; acc.y += fa0.y; acc.z += fa1.x; acc.w += fa1.y;
    }
    float inv = 1.0f / fmaxf((float)(s1 - s0), 1.0f);
    uint2 o;
    *(__half2*)&o.x = __floats2half2_rn(acc.x * inv, acc.y * inv);
    *(__half2*)&o.y = __floats2half2_rn(acc.z * inv, acc.w * inv);
    ((uint2*)g_agg16)[(size_t)gw * 32 + lane] = o;
    if (BN) {
        // materialize this node's relu(bn(h)) row for the self path
        uint2 vs = __ldg(f + (size_t)gw * 32 + lane);
        float2 s0f = __half22float2(*(__half2*)&vs.x);
        float2 s1f = __half22float2(*(__half2*)&vs.y);
        s0f.x = fmaxf(fmaf(s0f.x, sc.x, sh.x), 0.f);
        s0f.y = fmaxf(fmaf(s0f.y, sc.y, sh.y), 0.f);
        s1f.x = fmaxf(fmaf(s1f.x, sc.z, sh.z), 0.f);
        s1f.y = fmaxf(fmaf(s1f.y, sc.w, sh.w), 0.f);
        uint2 so;
        *(__half2*)&so.x = __floats2half2_rn(s0f.x, s0f.y);
        *(__half2*)&so.y = __floats2half2_rn(s1f.x, s1f.y);
        rbh[(size_t)gw * 32 + lane] = so;
    }
}

// ---------------- HMMA node transform ----------------
template<bool OUT_HALF>
__global__ void __launch_bounds__(256, 2)
mma_transform_k(const uint32_t* __restrict__ aggH,   // [m][64] half2-as-u32
                const uint32_t* __restrict__ selfH,
                const uint2* __restrict__ bfrag,     // 8192 x 8B fragments
                const float* __restrict__ bias,
                float* __restrict__ outF, __half2* __restrict__ outH,
                int nNodes, int ntiles) {
    extern __shared__ char smraw[];
    uint2* sB = (uint2*)smraw;                        // 64KB
    float* sBias = (float*)(smraw + 65536);
    int tid = threadIdx.x;
    for (int i = tid; i < 8192; i += 256) sB[i] = __ldg(bfrag + i);
    if (tid < 128) sBias[tid] = __ldg(bias + tid);
    __syncthreads();

    int warp = tid >> 5, lane = tid & 31;
    int r = lane >> 2, c = lane & 3;

    for (int tile = blockIdx.x; tile < ntiles; tile += gridDim.x) {
        int m0 = tile * 128 + warp * 16;
        size_t row0 = (size_t)min(m0 + r,     nNodes - 1);
        size_t row1 = (size_t)min(m0 + r + 8, nNodes - 1);
        const uint32_t* p0a = aggH  + row0 * 64 + c;
        const uint32_t* p1a = aggH  + row1 * 64 + c;
        const uint32_t* p0s = selfH + row0 * 64 + c;
        const uint32_t* p1s = selfH + row1 * 64 + c;

        float acc[16][4];
        #pragma unroll
        for (int nt = 0; nt < 16; nt++)
            #pragma unroll
            for (int q = 0; q < 4; q++) acc[nt][q] = 0.f;

        #pragma unroll
        for (int ks = 0; ks < 16; ks++) {
            const uint32_t* p0 = (ks < 8) ? p0a + ks * 8 : p0s + (ks - 8) * 8;
            const uint32_t* p1 = (ks < 8) ? p1a + ks * 8 : p1s + (ks - 8) * 8;
            uint32_t a0 = __ldg(p0), a2 = __ldg(p0 + 4);
            uint32_t a1 = __ldg(p1), a3 = __ldg(p1 + 4);
            const uint2* bp = sB + ks * 512 + lane;
            #pragma unroll
            for (int nt = 0; nt < 16; nt++) {
                uint2 b = bp[nt * 32];
                mma16816(acc[nt], a0, a1, a2, a3, b.x, b.y);
            }
        }

        bool ok0 = (m0 + r)     < nNodes;
        bool ok1 = (m0 + r + 8) < nNodes;
        #pragma unroll
        for (int nt = 0; nt < 16; nt++) {
            int j = nt * 8 + 2 * c;
            float b0 = sBias[j], b1 = sBias[j + 1];
            float v0 = acc[nt][0] + b0, v1 = acc[nt][1] + b1;
            float v2 = acc[nt][2] + b0, v3 = acc[nt][3] + b1;
            if (OUT_HALF) {
                if (ok0) outH[(size_t)(m0 + r)     * 64 + (j >> 1)] = __floats2half2_rn(v0, v1);
                if (ok1) outH[(size_t)(m0 + r + 8) * 64 + (j >> 1)] = __floats2half2_rn(v2, v3);
            } else {
                if (ok0) *(float2*)(outF + (size_t)(m0 + r)     * 128 + j) = make_float2(v0, v1);
                if (ok1) *(float2*)(outF + (size_t)(m0 + r + 8) * 128 + j) = make_float2(v2, v3);
            }
        }
    }
}

// ---------------- BN stats + finalize (last-block), self-resetting --------------
__global__ void stats_k(const float* __restrict__ gamma,
                        const float* __restrict__ beta, float invN, int N) {
    int c2  = threadIdx.x & 63;
    int sub = threadIdx.x >> 6;      // 0..3
    float sx = 0.f, sy = 0.f, qx = 0.f, qy = 0.f;
    for (int row = blockIdx.x * 4 + sub; row < N; row += gridDim.x * 4) {
        float2 f = __half22float2(g_h16[(size_t)row * 64 + c2]);
        sx += f.x; sy += f.y; qx += f.x * f.x; qy += f.y * f.y;
    }
    red_add1(g_colsum   + 2 * c2,     sx);
    red_add1(g_colsum   + 2 * c2 + 1, sy);
    red_add1(g_colsumsq + 2 * c2,     qx);
    red_add1(g_colsumsq + 2 * c2 + 1, qy);
    __threadfence();
    __shared__ int isLast;
    __syncthreads();
    if (threadIdx.x == 0)
        isLast = (atomicAdd(&g_done, 1) == gridDim.x - 1);
    __syncthreads();
    if (isLast && threadIdx.x < 128) {
        int j = threadIdx.x;
        float mu  = __ldcg(g_colsum + j) * invN;
        float var = __ldcg(g_colsumsq + j) * invN - mu * mu;
        float sc  = __ldg(gamma + j) * rsqrtf(var + BN_EPS);
        g_scale[j] = sc;
        g_shift[j] = fmaf(-mu, sc, __ldg(beta + j));
        g_colsum[j] = 0.f;           // reset for next replay
        g_colsumsq[j] = 0.f;
        if (j == 0) g_done = 0;
    }
}

// ---------------- launch ----------------
extern "C" void kernel_launch(void* const* d_in, const int* in_sizes, int n_in,
                              void* d_out, int out_size) {
    const float* x     = (const float*)d_in[0];
    const int*   ei    = (const int*)d_in[1];     // int32
    const float* w1l   = (const float*)d_in[2];
    const float* b1l   = (const float*)d_in[3];
    const float* w1r   = (const float*)d_in[4];
    const float* w2l   = (const float*)d_in[5];
    const float* b2l   = (const float*)d_in[6];
    const float* w2r   = (const float*)d_in[7];
    const float* gamma = (const float*)d_in[8];
    const float* beta  = (const float*)d_in[9];
    float*       out   = (float*)d_out;

    int N = in_sizes[0] / D;
    int E = in_sizes[1] / 2;
    int ntiles = (N + 127) / 128;

    void *p_x16, *p_h16, *p_agg16, *p_bf1, *p_bf2;
    cudaGetSymbolAddress(&p_x16,   g_x16);
    cudaGetSymbolAddress(&p_h16,   g_h16);
    cudaGetSymbolAddress(&p_agg16, g_agg16);
    cudaGetSymbolAddress(&p_bf1,   g_bf1);
    cudaGetSymbolAddress(&p_bf2,   g_bf2);

    int smem = 65536 + 512;
    cudaFuncSetAttribute(mma_transform_k<true>,
                         cudaFuncAttributeMaxDynamicSharedMemorySize, smem);
    cudaFuncSetAttribute(mma_transform_k<false>,
                         cudaFuncAttributeMaxDynamicSharedMemorySize, smem);

    // fused setup: 64 bfrag blocks + conv blocks (counters self-reset elsewhere)
    int cb = (N * 32 + 255) / 256;
    setup_k<<<64 + cb, 256>>>(x, w1l, w1r, w2l, w2r, N);

    // CSR build (reused by both layers)
    int egrid = (E + 255) / 256;
    hist_k<<<egrid, 256>>>(ei, E);
    scan_local_k<<<NBLK, SCAN_B>>>(N);
    scan_add_k<<<(N + 256) / 256, 256>>>(N, E);
    fill_k<<<egrid, 256>>>(ei, E);

    int ggrid = (N * 32 + 255) / 256;

    // layer 1: h = mean(x_nbr)@W1l + b1 + x@W1r   (fp16 inputs, fp32 acc)
    gather_k<false><<<ggrid, 256>>>((const __half2*)p_x16, nullptr, N);
    mma_transform_k<true><<<TGRID, 256, smem>>>(
        (const uint32_t*)p_agg16, (const uint32_t*)p_x16,
        (const uint2*)p_bf1, b1l, nullptr, (__half2*)p_h16, N, ntiles);

    // BN stats + finalize (fused, self-resetting)
    stats_k<<<148, 256>>>(gamma, beta, 1.0f / (float)N, N);

    // layer 2: gather applies relu(bn(.)) pre-mean and writes rbh (reuses g_x16)
    gather_k<true><<<ggrid, 256>>>((const __half2*)p_h16, (uint2*)p_x16, N);
    mma_transform_k<false><<<TGRID, 256, smem>>>(
        (const uint32_t*)p_agg16, (const uint32_t*)p_x16,
        (const uint2*)p_bf2, b2l, out, nullptr, N, ntiles);
}